// round 1
// baseline (speedup 1.0000x reference)
#include <cuda_runtime.h>
#include <math.h>

#define B_SZ   4
#define S_LEN  2048
#define DIM    1024
#define NH     16
#define HD     64
#define MROWS  (B_SZ * S_LEN)   /* 8192 */

// ---------------- scratch (device globals: no allocation allowed) -----------
__device__ float g_Qp[MROWS * DIM];   // x @ wq.T   [b,s,h*d]
__device__ float g_Kp[MROWS * DIM];
__device__ float g_Vp[MROWS * DIM];
__device__ float g_Qr[MROWS * DIM];   // rope'd, [bh, s, d]
__device__ float g_Kr[MROWS * DIM];
__device__ float g_Vr[MROWS * DIM];
__device__ float g_O [MROWS * DIM];   // attention out, [b, s, h*d]

// ---------------- fp32 SGEMM: C[m][n] = sum_k A[m][k] * B[n][k] -------------
// BM=BN=128, BK=8, 256 threads, 8x8 micro-tile.
__global__ __launch_bounds__(256) void sgemm_nt(
    const float* __restrict__ A, const float* __restrict__ B,
    float* __restrict__ C, int M, int N, int K)
{
    __shared__ float As[8][132];
    __shared__ float Bs[8][132];
    const int tid   = threadIdx.x;
    const int mtile = blockIdx.y, ntile = blockIdx.x;
    const float* Ab = A + (size_t)mtile * 128 * K;
    const float* Bb = B + (size_t)ntile * 128 * K;
    const int lrow = tid >> 1;
    const int lk   = (tid & 1) * 4;
    const int tr   = (tid >> 4) * 8;
    const int tc   = (tid & 15) * 8;

    float acc[8][8];
#pragma unroll
    for (int i = 0; i < 8; i++)
#pragma unroll
        for (int j = 0; j < 8; j++) acc[i][j] = 0.f;

    for (int k0 = 0; k0 < K; k0 += 8) {
        float4 a4 = *(const float4*)&Ab[(size_t)lrow * K + k0 + lk];
        float4 b4 = *(const float4*)&Bb[(size_t)lrow * K + k0 + lk];
        As[lk + 0][lrow] = a4.x; As[lk + 1][lrow] = a4.y;
        As[lk + 2][lrow] = a4.z; As[lk + 3][lrow] = a4.w;
        Bs[lk + 0][lrow] = b4.x; Bs[lk + 1][lrow] = b4.y;
        Bs[lk + 2][lrow] = b4.z; Bs[lk + 3][lrow] = b4.w;
        __syncthreads();
#pragma unroll
        for (int kk = 0; kk < 8; kk++) {
            float ar[8], br[8];
            *(float4*)&ar[0] = *(const float4*)&As[kk][tr];
            *(float4*)&ar[4] = *(const float4*)&As[kk][tr + 4];
            *(float4*)&br[0] = *(const float4*)&Bs[kk][tc];
            *(float4*)&br[4] = *(const float4*)&Bs[kk][tc + 4];
#pragma unroll
            for (int i = 0; i < 8; i++)
#pragma unroll
                for (int j = 0; j < 8; j++)
                    acc[i][j] = fmaf(ar[i], br[j], acc[i][j]);
        }
        __syncthreads();
    }
    float* Cb = C + (size_t)(mtile * 128 + tr) * N + ntile * 128 + tc;
#pragma unroll
    for (int i = 0; i < 8; i++) {
        *(float4*)&Cb[(size_t)i * N + 0] =
            make_float4(acc[i][0], acc[i][1], acc[i][2], acc[i][3]);
        *(float4*)&Cb[(size_t)i * N + 4] =
            make_float4(acc[i][4], acc[i][5], acc[i][6], acc[i][7]);
    }
}

// ------------- RoPE + reshape [b,s,h*d] -> [bh, s, d] (V: reshape only) -----
__global__ __launch_bounds__(256) void rope_reshape(
    const float* __restrict__ Q, const float* __restrict__ Kk,
    const float* __restrict__ V,
    float* __restrict__ Qr, float* __restrict__ Kr, float* __restrict__ Vr)
{
    int idx = blockIdx.x * blockDim.x + threadIdx.x;   // B*S*NH*32 = 4194304
    int i = idx & 31;
    int h = (idx >> 5) & 15;
    int s = (idx >> 9) & 2047;
    int b = idx >> 20;

    size_t src = ((size_t)(b * S_LEN + s)) * DIM + h * HD + 2 * i;
    size_t dst = ((size_t)((b * NH + h) * S_LEN + s)) * HD + 2 * i;

    float inv = powf(10000.f, -(float)(2 * i) / (float)HD);
    float sn, cs;
    sincosf((float)s * inv, &sn, &cs);

    float2 q = *(const float2*)&Q[src];
    float2 k = *(const float2*)&Kk[src];
    float2 v = *(const float2*)&V[src];
    *(float2*)&Qr[dst] = make_float2(q.x * cs - q.y * sn, q.x * sn + q.y * cs);
    *(float2*)&Kr[dst] = make_float2(k.x * cs - k.y * sn, k.x * sn + k.y * cs);
    *(float2*)&Vr[dst] = v;
}

// ---------------- flash attention, fp32 -------------------------------------
// Block = 256 threads handles 64 queries of one (b,h). Key tiles of 64.
// Thread grid 16x16: trow owns 4 q rows, tcol owns 4 k cols (phase1) /
// 4 d cols (phase2). Online softmax; row stats reduced over 16-lane groups.
#define PADR 68   // row stride in floats (padded, 16B-aligned)

__global__ __launch_bounds__(256) void attn_kernel(
    const float* __restrict__ Qr, const float* __restrict__ Kr,
    const float* __restrict__ Vr, const int* __restrict__ seq_lens,
    float* __restrict__ O)
{
    extern __shared__ float sm[];
    float* Qsm = sm;                 // [d][q]  64*PADR
    float* Ksm = sm + 64 * PADR;     // [d][k]
    float* Vsm = sm + 2 * 64 * PADR; // [k][d]
    float* Psm = sm + 3 * 64 * PADR; // [k][q]

    const int tid = threadIdx.x;
    const int qt = blockIdx.x, h = blockIdx.y, b = blockIdx.z;
    const int q0 = qt * 64;
    const int L  = seq_lens[b];
    const int bh = b * NH + h;
    const float* Qb = Qr + ((size_t)bh * S_LEN + q0) * HD;
    const float* Kb = Kr + (size_t)bh * S_LEN * HD;
    const float* Vb = Vr + (size_t)bh * S_LEN * HD;

    // load Q tile transposed into Qsm[d][q]
#pragma unroll
    for (int it = 0; it < 4; it++) {
        int f = it * 1024 + tid * 4;
        int r = f >> 6, d0 = f & 63;
        float4 v = *(const float4*)&Qb[(size_t)r * HD + d0];
        Qsm[(d0 + 0) * PADR + r] = v.x;
        Qsm[(d0 + 1) * PADR + r] = v.y;
        Qsm[(d0 + 2) * PADR + r] = v.z;
        Qsm[(d0 + 3) * PADR + r] = v.w;
    }

    const int trow = tid >> 4, tcol = tid & 15;
    float m[4], lsum[4], o[4][4];
#pragma unroll
    for (int qi = 0; qi < 4; qi++) {
        m[qi] = -1e30f; lsum[qi] = 0.f;
#pragma unroll
        for (int di = 0; di < 4; di++) o[qi][di] = 0.f;
    }

    // if all 64 queries are below L, they only see keys [0, L)
    const int ntiles = (q0 + 63 < L) ? ((L + 63) >> 6) : (S_LEN >> 6);

    for (int kt = 0; kt < ntiles; kt++) {
        __syncthreads();   // previous phase-2 reads complete
        const float* Kt = Kb + (size_t)kt * 64 * HD;
        const float* Vt = Vb + (size_t)kt * 64 * HD;
#pragma unroll
        for (int it = 0; it < 4; it++) {
            int f = it * 1024 + tid * 4;
            int r = f >> 6, d0 = f & 63;
            float4 kv = *(const float4*)&Kt[(size_t)r * HD + d0];
            Ksm[(d0 + 0) * PADR + r] = kv.x;
            Ksm[(d0 + 1) * PADR + r] = kv.y;
            Ksm[(d0 + 2) * PADR + r] = kv.z;
            Ksm[(d0 + 3) * PADR + r] = kv.w;
            float4 vv = *(const float4*)&Vt[(size_t)r * HD + d0];
            *(float4*)&Vsm[r * PADR + d0] = vv;
        }
        __syncthreads();

        // phase 1: S = Q @ K^T
        float sacc[4][4];
#pragma unroll
        for (int qi = 0; qi < 4; qi++)
#pragma unroll
            for (int ki = 0; ki < 4; ki++) sacc[qi][ki] = 0.f;
#pragma unroll 8
        for (int d = 0; d < HD; d++) {
            float4 qv = *(const float4*)&Qsm[d * PADR + trow * 4];
            float4 kv = *(const float4*)&Ksm[d * PADR + tcol * 4];
            float qa[4] = {qv.x, qv.y, qv.z, qv.w};
            float ka[4] = {kv.x, kv.y, kv.z, kv.w};
#pragma unroll
            for (int qi = 0; qi < 4; qi++)
#pragma unroll
                for (int ki = 0; ki < 4; ki++)
                    sacc[qi][ki] = fmaf(qa[qi], ka[ki], sacc[qi][ki]);
        }

        // mask + online softmax
        const int kbase = kt * 64 + tcol * 4;
        float ptile[4][4];
#pragma unroll
        for (int qi = 0; qi < 4; qi++) {
            const int qg = q0 + trow * 4 + qi;
            const int kmax = (qg < L) ? L : S_LEN;
            float sv[4], mx = -1e30f;
#pragma unroll
            for (int ki = 0; ki < 4; ki++) {
                float s = sacc[qi][ki] * 0.125f;   // 1/sqrt(64)
                if (kbase + ki >= kmax) s = -1e30f;
                sv[ki] = s;
                mx = fmaxf(mx, s);
            }
            // max over 16-lane row group (stays within the group: offsets < 16)
            mx = fmaxf(mx, __shfl_xor_sync(0xffffffffu, mx, 8));
            mx = fmaxf(mx, __shfl_xor_sync(0xffffffffu, mx, 4));
            mx = fmaxf(mx, __shfl_xor_sync(0xffffffffu, mx, 2));
            mx = fmaxf(mx, __shfl_xor_sync(0xffffffffu, mx, 1));
            const float mnew = fmaxf(m[qi], mx);
            const float a = expf(m[qi] - mnew);
            float ls = 0.f;
#pragma unroll
            for (int ki = 0; ki < 4; ki++) {
                float p = expf(sv[ki] - mnew);
                ptile[qi][ki] = p;
                ls += p;
            }
            ls += __shfl_xor_sync(0xffffffffu, ls, 8);
            ls += __shfl_xor_sync(0xffffffffu, ls, 4);
            ls += __shfl_xor_sync(0xffffffffu, ls, 2);
            ls += __shfl_xor_sync(0xffffffffu, ls, 1);
            lsum[qi] = lsum[qi] * a + ls;
            m[qi] = mnew;
#pragma unroll
            for (int di = 0; di < 4; di++) o[qi][di] *= a;
        }

        // write P -> Psm[k][q]
#pragma unroll
        for (int ki = 0; ki < 4; ki++) {
            float4 p4 = make_float4(ptile[0][ki], ptile[1][ki],
                                    ptile[2][ki], ptile[3][ki]);
            *(float4*)&Psm[(tcol * 4 + ki) * PADR + trow * 4] = p4;
        }
        __syncthreads();

        // phase 2: O += P @ V
#pragma unroll 8
        for (int k = 0; k < 64; k++) {
            float4 pv = *(const float4*)&Psm[k * PADR + trow * 4];
            float4 vv = *(const float4*)&Vsm[k * PADR + tcol * 4];
            float pa[4] = {pv.x, pv.y, pv.z, pv.w};
            float va[4] = {vv.x, vv.y, vv.z, vv.w};
#pragma unroll
            for (int qi = 0; qi < 4; qi++)
#pragma unroll
                for (int di = 0; di < 4; di++)
                    o[qi][di] = fmaf(pa[qi], va[di], o[qi][di]);
        }
    }

    // epilogue: O /= l, write to [b, s, h*d]
#pragma unroll
    for (int qi = 0; qi < 4; qi++) {
        const float inv = 1.f / lsum[qi];
        const int qg = q0 + trow * 4 + qi;
        float* dst = O + ((size_t)b * S_LEN + qg) * DIM + h * HD + tcol * 4;
        *(float4*)dst = make_float4(o[qi][0] * inv, o[qi][1] * inv,
                                    o[qi][2] * inv, o[qi][3] * inv);
    }
}

// ---------------- launch -----------------------------------------------------
extern "C" void kernel_launch(void* const* d_in, const int* in_sizes, int n_in,
                              void* d_out, int out_size)
{
    const float* x   = (const float*)d_in[0];
    const int*   seq = (const int*)  d_in[1];
    const float* wq  = (const float*)d_in[2];
    const float* wk  = (const float*)d_in[3];
    const float* wv  = (const float*)d_in[4];
    const float* wo  = (const float*)d_in[5];
    float* out = (float*)d_out;

    float *Qp, *Kp, *Vp, *Qr, *Kr, *Vr, *Oa;
    cudaGetSymbolAddress((void**)&Qp, g_Qp);
    cudaGetSymbolAddress((void**)&Kp, g_Kp);
    cudaGetSymbolAddress((void**)&Vp, g_Vp);
    cudaGetSymbolAddress((void**)&Qr, g_Qr);
    cudaGetSymbolAddress((void**)&Kr, g_Kr);
    cudaGetSymbolAddress((void**)&Vr, g_Vr);
    cudaGetSymbolAddress((void**)&Oa, g_O);

    dim3 gg(DIM / 128, MROWS / 128);
    sgemm_nt<<<gg, 256>>>(x, wq, Qp, MROWS, DIM, DIM);
    sgemm_nt<<<gg, 256>>>(x, wk, Kp, MROWS, DIM, DIM);
    sgemm_nt<<<gg, 256>>>(x, wv, Vp, MROWS, DIM, DIM);

    rope_reshape<<<(B_SZ * S_LEN * NH * 32) / 256, 256>>>(Qp, Kp, Vp, Qr, Kr, Vr);

    const int smem = 4 * 64 * PADR * sizeof(float);   // 69632 B
    cudaFuncSetAttribute(attn_kernel,
                         cudaFuncAttributeMaxDynamicSharedMemorySize, smem);
    attn_kernel<<<dim3(S_LEN / 64, NH, B_SZ), 256, smem>>>(Qr, Kr, Vr, seq, Oa);

    sgemm_nt<<<gg, 256>>>(Oa, wo, out, MROWS, DIM, DIM);
}

// round 5
// speedup vs baseline: 1.5910x; 1.5910x over previous
#include <cuda_runtime.h>
#include <math.h>
#include <stdint.h>

#define B_SZ   4
#define S_LEN  2048
#define DIM    1024
#define NH     16
#define HD     64
#define MROWS  (B_SZ * S_LEN)   /* 8192 */

// ---------------- scratch (device globals: no allocation allowed) -----------
__device__ float g_Qp[MROWS * DIM];
__device__ float g_Kp[MROWS * DIM];
__device__ float g_Vp[MROWS * DIM];
__device__ float g_Qr[MROWS * DIM];
__device__ float g_Kr[MROWS * DIM];
__device__ float g_Vr[MROWS * DIM];
__device__ float g_O [MROWS * DIM];

// ======================= helpers ============================================
__device__ __forceinline__ uint32_t f2tf32(float x) {
    uint32_t u;
    asm("cvt.rna.tf32.f32 %0, %1;" : "=r"(u) : "f"(x));
    return u;
}

// D += A@B via m16n8k8 tf32 HMMA (fp32 accum). A row-major frag, B col-major frag.
__device__ __forceinline__ void mma_tf32(
    float* d, const uint32_t* a, const uint32_t* b)
{
    asm volatile(
        "mma.sync.aligned.m16n8k8.row.col.f32.tf32.tf32.f32 "
        "{%0,%1,%2,%3}, {%4,%5,%6,%7}, {%8,%9}, {%0,%1,%2,%3};"
        : "+f"(d[0]), "+f"(d[1]), "+f"(d[2]), "+f"(d[3])
        : "r"(a[0]), "r"(a[1]), "r"(a[2]), "r"(a[3]),
          "r"(b[0]), "r"(b[1]));
}

// ============ tf32 HMMA GEMM: C[m][n] = sum_k A[m][k] * B[n][k] =============
// BM=BN=128, BK=32, 256 threads (8 warps, 2m x 4n), warp tile 64x32.
#define GBK      32
#define GSTRIDE  36                     /* smem row stride in 4B words */
#define GTILE    (128 * GSTRIDE)        /* words per stage per operand */
#define G_SMEM_TOTAL (4 * GTILE * 4)    /* 2 ops x 2 stages, bytes = 73728 */

__global__ __launch_bounds__(256) void gemm_mma(
    const float* __restrict__ A, const float* __restrict__ B,
    float* __restrict__ C)
{
    extern __shared__ uint32_t smw[];
    uint32_t* As = smw;                 // [2][128][GSTRIDE]
    uint32_t* Bs = smw + 2 * GTILE;

    const int tid  = threadIdx.x, wid = tid >> 5, lane = tid & 31;
    const int wm   = wid & 1;           // 0..1 -> 64 rows each
    const int wn   = wid >> 1;          // 0..3 -> 32 cols each
    const int g    = lane >> 2;         // group 0..7
    const int tg   = lane & 3;          // thread-in-group 0..3
    const int ntile = blockIdx.x, mtile = blockIdx.y;
    const int K = DIM, N = DIM;
    const float* Ag = A + (size_t)mtile * 128 * K;
    const float* Bg = B + (size_t)ntile * 128 * K;

    float acc[4][4][4];
#pragma unroll
    for (int mt = 0; mt < 4; mt++)
#pragma unroll
        for (int nt = 0; nt < 4; nt++)
#pragma unroll
            for (int r = 0; r < 4; r++) acc[mt][nt][r] = 0.f;

    // gmem tile: 128 rows x 32 cols = 1024 float4; 4 per thread.
    float4 ra[4], rb[4];

#define G_LDG(it) do {                                                         \
    const int _k0 = (it) * GBK;                                                \
    _Pragma("unroll")                                                          \
    for (int j = 0; j < 4; j++) {                                              \
        int i = tid + j * 256;                                                 \
        int r = i >> 3, c = i & 7;                                             \
        ra[j] = *(const float4*)&Ag[(size_t)r * K + _k0 + c * 4];              \
        rb[j] = *(const float4*)&Bg[(size_t)r * K + _k0 + c * 4];              \
    }                                                                          \
} while (0)

#define G_STS(st) do {                                                         \
    uint32_t* _pa = As + (st) * GTILE;                                         \
    uint32_t* _pb = Bs + (st) * GTILE;                                         \
    _Pragma("unroll")                                                          \
    for (int j = 0; j < 4; j++) {                                              \
        int i = tid + j * 256;                                                 \
        int r = i >> 3, c = i & 7;                                             \
        uint4 ua = make_uint4(f2tf32(ra[j].x), f2tf32(ra[j].y),                \
                              f2tf32(ra[j].z), f2tf32(ra[j].w));               \
        uint4 ub = make_uint4(f2tf32(rb[j].x), f2tf32(rb[j].y),                \
                              f2tf32(rb[j].z), f2tf32(rb[j].w));               \
        *(uint4*)&_pa[r * GSTRIDE + c * 4] = ua;                               \
        *(uint4*)&_pb[r * GSTRIDE + c * 4] = ub;                               \
    }                                                                          \
} while (0)

    const int niters = K / GBK;         // 32
    G_LDG(0);
    G_STS(0);
    __syncthreads();

    for (int it = 0; it < niters; it++) {
        const int st = it & 1;
        if (it + 1 < niters) G_LDG(it + 1);

        const uint32_t* pa = As + st * GTILE;
        const uint32_t* pb = Bs + st * GTILE;
#pragma unroll
        for (int ks = 0; ks < 4; ks++) {
            const int kk = ks * 8;
            uint32_t af[4][4], bf[4][2];
#pragma unroll
            for (int mt = 0; mt < 4; mt++) {
                const int row = wm * 64 + mt * 16;
                af[mt][0] = pa[(row + g)     * GSTRIDE + kk + tg];
                af[mt][1] = pa[(row + g + 8) * GSTRIDE + kk + tg];
                af[mt][2] = pa[(row + g)     * GSTRIDE + kk + tg + 4];
                af[mt][3] = pa[(row + g + 8) * GSTRIDE + kk + tg + 4];
            }
#pragma unroll
            for (int nt = 0; nt < 4; nt++) {
                const int col = wn * 32 + nt * 8;
                bf[nt][0] = pb[(col + g) * GSTRIDE + kk + tg];
                bf[nt][1] = pb[(col + g) * GSTRIDE + kk + tg + 4];
            }
#pragma unroll
            for (int mt = 0; mt < 4; mt++)
#pragma unroll
                for (int nt = 0; nt < 4; nt++)
                    mma_tf32(acc[mt][nt], af[mt], bf[nt]);
        }

        if (it + 1 < niters) G_STS((it + 1) & 1);
        __syncthreads();
    }

    // epilogue: write accumulators
#pragma unroll
    for (int mt = 0; mt < 4; mt++) {
        const int row = mtile * 128 + wm * 64 + mt * 16 + g;
#pragma unroll
        for (int nt = 0; nt < 4; nt++) {
            const int col = ntile * 128 + wn * 32 + nt * 8 + 2 * tg;
            *(float2*)&C[(size_t)row * N + col] =
                make_float2(acc[mt][nt][0], acc[mt][nt][1]);
            *(float2*)&C[(size_t)(row + 8) * N + col] =
                make_float2(acc[mt][nt][2], acc[mt][nt][3]);
        }
    }
}

// ------------- RoPE + reshape [b,s,h*d] -> [bh, s, d] (V: reshape only) -----
__global__ __launch_bounds__(256) void rope_reshape(
    const float* __restrict__ Q, const float* __restrict__ Kk,
    const float* __restrict__ V,
    float* __restrict__ Qr, float* __restrict__ Kr, float* __restrict__ Vr)
{
    int idx = blockIdx.x * blockDim.x + threadIdx.x;
    int i = idx & 31;
    int h = (idx >> 5) & 15;
    int s = (idx >> 9) & 2047;
    int b = idx >> 20;

    size_t src = ((size_t)(b * S_LEN + s)) * DIM + h * HD + 2 * i;
    size_t dst = ((size_t)((b * NH + h) * S_LEN + s)) * HD + 2 * i;

    float inv = powf(10000.f, -(float)(2 * i) / (float)HD);
    float sn, cs;
    sincosf((float)s * inv, &sn, &cs);

    float2 q = *(const float2*)&Q[src];
    float2 k = *(const float2*)&Kk[src];
    float2 v = *(const float2*)&V[src];
    *(float2*)&Qr[dst] = make_float2(q.x * cs - q.y * sn, q.x * sn + q.y * cs);
    *(float2*)&Kr[dst] = make_float2(k.x * cs - k.y * sn, k.x * sn + k.y * cs);
    *(float2*)&Vr[dst] = v;
}

// ---------------- flash attention, fp32 (known-good from R1) ----------------
#define PADR 68

__global__ __launch_bounds__(256) void attn_kernel(
    const float* __restrict__ Qr, const float* __restrict__ Kr,
    const float* __restrict__ Vr, const int* __restrict__ seq_lens,
    float* __restrict__ O)
{
    extern __shared__ float sm[];
    float* Qsm = sm;
    float* Ksm = sm + 64 * PADR;
    float* Vsm = sm + 2 * 64 * PADR;
    float* Psm = sm + 3 * 64 * PADR;

    const int tid = threadIdx.x;
    const int qt = blockIdx.x, h = blockIdx.y, b = blockIdx.z;
    const int q0 = qt * 64;
    const int L  = seq_lens[b];
    const int bh = b * NH + h;
    const float* Qb = Qr + ((size_t)bh * S_LEN + q0) * HD;
    const float* Kb = Kr + (size_t)bh * S_LEN * HD;
    const float* Vb = Vr + (size_t)bh * S_LEN * HD;

#pragma unroll
    for (int it = 0; it < 4; it++) {
        int f = it * 1024 + tid * 4;
        int r = f >> 6, d0 = f & 63;
        float4 v = *(const float4*)&Qb[(size_t)r * HD + d0];
        Qsm[(d0 + 0) * PADR + r] = v.x;
        Qsm[(d0 + 1) * PADR + r] = v.y;
        Qsm[(d0 + 2) * PADR + r] = v.z;
        Qsm[(d0 + 3) * PADR + r] = v.w;
    }

    const int trow = tid >> 4, tcol = tid & 15;
    float m[4], lsum[4], o[4][4];
#pragma unroll
    for (int qi = 0; qi < 4; qi++) {
        m[qi] = -1e30f; lsum[qi] = 0.f;
#pragma unroll
        for (int di = 0; di < 4; di++) o[qi][di] = 0.f;
    }

    const int ntiles = (q0 + 63 < L) ? ((L + 63) >> 6) : (S_LEN >> 6);

    for (int kt = 0; kt < ntiles; kt++) {
        __syncthreads();
        const float* Kt = Kb + (size_t)kt * 64 * HD;
        const float* Vt = Vb + (size_t)kt * 64 * HD;
#pragma unroll
        for (int it = 0; it < 4; it++) {
            int f = it * 1024 + tid * 4;
            int r = f >> 6, d0 = f & 63;
            float4 kv = *(const float4*)&Kt[(size_t)r * HD + d0];
            Ksm[(d0 + 0) * PADR + r] = kv.x;
            Ksm[(d0 + 1) * PADR + r] = kv.y;
            Ksm[(d0 + 2) * PADR + r] = kv.z;
            Ksm[(d0 + 3) * PADR + r] = kv.w;
            float4 vv = *(const float4*)&Vt[(size_t)r * HD + d0];
            *(float4*)&Vsm[r * PADR + d0] = vv;
        }
        __syncthreads();

        float sacc[4][4];
#pragma unroll
        for (int qi = 0; qi < 4; qi++)
#pragma unroll
            for (int ki = 0; ki < 4; ki++) sacc[qi][ki] = 0.f;
#pragma unroll 8
        for (int d = 0; d < HD; d++) {
            float4 qv = *(const float4*)&Qsm[d * PADR + trow * 4];
            float4 kv = *(const float4*)&Ksm[d * PADR + tcol * 4];
            float qa[4] = {qv.x, qv.y, qv.z, qv.w};
            float ka[4] = {kv.x, kv.y, kv.z, kv.w};
#pragma unroll
            for (int qi = 0; qi < 4; qi++)
#pragma unroll
                for (int ki = 0; ki < 4; ki++)
                    sacc[qi][ki] = fmaf(qa[qi], ka[ki], sacc[qi][ki]);
        }

        const int kbase = kt * 64 + tcol * 4;
        float ptile[4][4];
#pragma unroll
        for (int qi = 0; qi < 4; qi++) {
            const int qg = q0 + trow * 4 + qi;
            const int kmax = (qg < L) ? L : S_LEN;
            float sv[4], mx = -1e30f;
#pragma unroll
            for (int ki = 0; ki < 4; ki++) {
                float s = sacc[qi][ki] * 0.125f;
                if (kbase + ki >= kmax) s = -1e30f;
                sv[ki] = s;
                mx = fmaxf(mx, s);
            }
            mx = fmaxf(mx, __shfl_xor_sync(0xffffffffu, mx, 8));
            mx = fmaxf(mx, __shfl_xor_sync(0xffffffffu, mx, 4));
            mx = fmaxf(mx, __shfl_xor_sync(0xffffffffu, mx, 2));
            mx = fmaxf(mx, __shfl_xor_sync(0xffffffffu, mx, 1));
            const float mnew = fmaxf(m[qi], mx);
            const float a = expf(m[qi] - mnew);
            float ls = 0.f;
#pragma unroll
            for (int ki = 0; ki < 4; ki++) {
                float p = expf(sv[ki] - mnew);
                ptile[qi][ki] = p;
                ls += p;
            }
            ls += __shfl_xor_sync(0xffffffffu, ls, 8);
            ls += __shfl_xor_sync(0xffffffffu, ls, 4);
            ls += __shfl_xor_sync(0xffffffffu, ls, 2);
            ls += __shfl_xor_sync(0xffffffffu, ls, 1);
            lsum[qi] = lsum[qi] * a + ls;
            m[qi] = mnew;
#pragma unroll
            for (int di = 0; di < 4; di++) o[qi][di] *= a;
        }

#pragma unroll
        for (int ki = 0; ki < 4; ki++) {
            float4 p4 = make_float4(ptile[0][ki], ptile[1][ki],
                                    ptile[2][ki], ptile[3][ki]);
            *(float4*)&Psm[(tcol * 4 + ki) * PADR + trow * 4] = p4;
        }
        __syncthreads();

#pragma unroll 8
        for (int k = 0; k < 64; k++) {
            float4 pv = *(const float4*)&Psm[k * PADR + trow * 4];
            float4 vv = *(const float4*)&Vsm[k * PADR + tcol * 4];
            float pa[4] = {pv.x, pv.y, pv.z, pv.w};
            float va[4] = {vv.x, vv.y, vv.z, vv.w};
#pragma unroll
            for (int qi = 0; qi < 4; qi++)
#pragma unroll
                for (int di = 0; di < 4; di++)
                    o[qi][di] = fmaf(pa[qi], va[di], o[qi][di]);
        }
    }

#pragma unroll
    for (int qi = 0; qi < 4; qi++) {
        const float inv = 1.f / lsum[qi];
        const int qg = q0 + trow * 4 + qi;
        float* dst = O + ((size_t)b * S_LEN + qg) * DIM + h * HD + tcol * 4;
        *(float4*)dst = make_float4(o[qi][0] * inv, o[qi][1] * inv,
                                    o[qi][2] * inv, o[qi][3] * inv);
    }
}

// ---------------- launch -----------------------------------------------------
extern "C" void kernel_launch(void* const* d_in, const int* in_sizes, int n_in,
                              void* d_out, int out_size)
{
    const float* x   = (const float*)d_in[0];
    const int*   seq = (const int*)  d_in[1];
    const float* wq  = (const float*)d_in[2];
    const float* wk  = (const float*)d_in[3];
    const float* wv  = (const float*)d_in[4];
    const float* wo  = (const float*)d_in[5];
    float* out = (float*)d_out;

    float *Qp, *Kp, *Vp, *Qr, *Kr, *Vr, *Oa;
    cudaGetSymbolAddress((void**)&Qp, g_Qp);
    cudaGetSymbolAddress((void**)&Kp, g_Kp);
    cudaGetSymbolAddress((void**)&Vp, g_Vp);
    cudaGetSymbolAddress((void**)&Qr, g_Qr);
    cudaGetSymbolAddress((void**)&Kr, g_Kr);
    cudaGetSymbolAddress((void**)&Vr, g_Vr);
    cudaGetSymbolAddress((void**)&Oa, g_O);

    cudaFuncSetAttribute(gemm_mma,
                         cudaFuncAttributeMaxDynamicSharedMemorySize, G_SMEM_TOTAL);

    dim3 gg(DIM / 128, MROWS / 128);
    gemm_mma<<<gg, 256, G_SMEM_TOTAL>>>(x, wq, Qp);
    gemm_mma<<<gg, 256, G_SMEM_TOTAL>>>(x, wk, Kp);
    gemm_mma<<<gg, 256, G_SMEM_TOTAL>>>(x, wv, Vp);

    rope_reshape<<<(B_SZ * S_LEN * NH * 32) / 256, 256>>>(Qp, Kp, Vp, Qr, Kr, Vr);

    const int smem = 4 * 64 * PADR * sizeof(float);
    cudaFuncSetAttribute(attn_kernel,
                         cudaFuncAttributeMaxDynamicSharedMemorySize, smem);
    attn_kernel<<<dim3(S_LEN / 64, NH, B_SZ), 256, smem>>>(Qr, Kr, Vr, seq, Oa);

    gemm_mma<<<gg, 256, G_SMEM_TOTAL>>>(Oa, wo, out);
}

// round 7
// speedup vs baseline: 3.4852x; 2.1906x over previous
#include <cuda_runtime.h>
#include <math.h>
#include <stdint.h>

#define B_SZ   4
#define S_LEN  2048
#define DIM    1024
#define NH     16
#define HD     64
#define MROWS  (B_SZ * S_LEN)   /* 8192 */

// ---------------- scratch (device globals: no allocation allowed) -----------
__device__ float g_Qp[MROWS * DIM];
__device__ float g_Kp[MROWS * DIM];
__device__ float g_Vp[MROWS * DIM];
__device__ float g_Qr[MROWS * DIM];
__device__ float g_Kr[MROWS * DIM];
__device__ float g_Vr[MROWS * DIM];
__device__ float g_O [MROWS * DIM];

// ======================= helpers ============================================
__device__ __forceinline__ uint32_t f2tf32(float x) {
    uint32_t u;
    asm("cvt.rna.tf32.f32 %0, %1;" : "=r"(u) : "f"(x));
    return u;
}

// D += A@B via m16n8k8 tf32 HMMA (fp32 accum). A row-major frag, B col-major frag.
__device__ __forceinline__ void mma_tf32(
    float* d, const uint32_t* a, const uint32_t* b)
{
    asm volatile(
        "mma.sync.aligned.m16n8k8.row.col.f32.tf32.tf32.f32 "
        "{%0,%1,%2,%3}, {%4,%5,%6,%7}, {%8,%9}, {%0,%1,%2,%3};"
        : "+f"(d[0]), "+f"(d[1]), "+f"(d[2]), "+f"(d[3])
        : "r"(a[0]), "r"(a[1]), "r"(a[2]), "r"(a[3]),
          "r"(b[0]), "r"(b[1]));
}

// ============ tf32 HMMA GEMM: C[m][n] = sum_k A[m][k] * B[n][k] =============
// BM=BN=128, BK=32, 256 threads (8 warps, 2m x 4n), warp tile 64x32.
#define GBK      32
#define GSTRIDE  36
#define GTILE    (128 * GSTRIDE)
#define G_SMEM_TOTAL (4 * GTILE * 4)

__global__ __launch_bounds__(256) void gemm_mma(
    const float* __restrict__ A, const float* __restrict__ B,
    float* __restrict__ C)
{
    extern __shared__ uint32_t smw[];
    uint32_t* As = smw;
    uint32_t* Bs = smw + 2 * GTILE;

    const int tid  = threadIdx.x, wid = tid >> 5, lane = tid & 31;
    const int wm   = wid & 1;
    const int wn   = wid >> 1;
    const int g    = lane >> 2;
    const int tg   = lane & 3;
    const int ntile = blockIdx.x, mtile = blockIdx.y;
    const int K = DIM, N = DIM;
    const float* Ag = A + (size_t)mtile * 128 * K;
    const float* Bg = B + (size_t)ntile * 128 * K;

    float acc[4][4][4];
#pragma unroll
    for (int mt = 0; mt < 4; mt++)
#pragma unroll
        for (int nt = 0; nt < 4; nt++)
#pragma unroll
            for (int r = 0; r < 4; r++) acc[mt][nt][r] = 0.f;

    float4 ra[4], rb[4];

#define G_LDG(it) do {                                                         \
    const int _k0 = (it) * GBK;                                                \
    _Pragma("unroll")                                                          \
    for (int j = 0; j < 4; j++) {                                              \
        int i = tid + j * 256;                                                 \
        int r = i >> 3, c = i & 7;                                             \
        ra[j] = *(const float4*)&Ag[(size_t)r * K + _k0 + c * 4];              \
        rb[j] = *(const float4*)&Bg[(size_t)r * K + _k0 + c * 4];              \
    }                                                                          \
} while (0)

#define G_STS(st) do {                                                         \
    uint32_t* _pa = As + (st) * GTILE;                                         \
    uint32_t* _pb = Bs + (st) * GTILE;                                         \
    _Pragma("unroll")                                                          \
    for (int j = 0; j < 4; j++) {                                              \
        int i = tid + j * 256;                                                 \
        int r = i >> 3, c = i & 7;                                             \
        uint4 ua = make_uint4(f2tf32(ra[j].x), f2tf32(ra[j].y),                \
                              f2tf32(ra[j].z), f2tf32(ra[j].w));               \
        uint4 ub = make_uint4(f2tf32(rb[j].x), f2tf32(rb[j].y),                \
                              f2tf32(rb[j].z), f2tf32(rb[j].w));               \
        *(uint4*)&_pa[r * GSTRIDE + c * 4] = ua;                               \
        *(uint4*)&_pb[r * GSTRIDE + c * 4] = ub;                               \
    }                                                                          \
} while (0)

    const int niters = K / GBK;
    G_LDG(0);
    G_STS(0);
    __syncthreads();

    for (int it = 0; it < niters; it++) {
        const int st = it & 1;
        if (it + 1 < niters) G_LDG(it + 1);

        const uint32_t* pa = As + st * GTILE;
        const uint32_t* pb = Bs + st * GTILE;
#pragma unroll
        for (int ks = 0; ks < 4; ks++) {
            const int kk = ks * 8;
            uint32_t af[4][4], bf[4][2];
#pragma unroll
            for (int mt = 0; mt < 4; mt++) {
                const int row = wm * 64 + mt * 16;
                af[mt][0] = pa[(row + g)     * GSTRIDE + kk + tg];
                af[mt][1] = pa[(row + g + 8) * GSTRIDE + kk + tg];
                af[mt][2] = pa[(row + g)     * GSTRIDE + kk + tg + 4];
                af[mt][3] = pa[(row + g + 8) * GSTRIDE + kk + tg + 4];
            }
#pragma unroll
            for (int nt = 0; nt < 4; nt++) {
                const int col = wn * 32 + nt * 8;
                bf[nt][0] = pb[(col + g) * GSTRIDE + kk + tg];
                bf[nt][1] = pb[(col + g) * GSTRIDE + kk + tg + 4];
            }
#pragma unroll
            for (int mt = 0; mt < 4; mt++)
#pragma unroll
                for (int nt = 0; nt < 4; nt++)
                    mma_tf32(acc[mt][nt], af[mt], bf[nt]);
        }

        if (it + 1 < niters) G_STS((it + 1) & 1);
        __syncthreads();
    }

#pragma unroll
    for (int mt = 0; mt < 4; mt++) {
        const int row = mtile * 128 + wm * 64 + mt * 16 + g;
#pragma unroll
        for (int nt = 0; nt < 4; nt++) {
            const int col = ntile * 128 + wn * 32 + nt * 8 + 2 * tg;
            *(float2*)&C[(size_t)row * N + col] =
                make_float2(acc[mt][nt][0], acc[mt][nt][1]);
            *(float2*)&C[(size_t)(row + 8) * N + col] =
                make_float2(acc[mt][nt][2], acc[mt][nt][3]);
        }
    }
}

// ------------- RoPE + reshape [b,s,h*d] -> [bh, s, d] (V: reshape only) -----
__global__ __launch_bounds__(256) void rope_reshape(
    const float* __restrict__ Q, const float* __restrict__ Kk,
    const float* __restrict__ V,
    float* __restrict__ Qr, float* __restrict__ Kr, float* __restrict__ Vr)
{
    int idx = blockIdx.x * blockDim.x + threadIdx.x;
    int i = idx & 31;
    int h = (idx >> 5) & 15;
    int s = (idx >> 9) & 2047;
    int b = idx >> 20;

    size_t src = ((size_t)(b * S_LEN + s)) * DIM + h * HD + 2 * i;
    size_t dst = ((size_t)((b * NH + h) * S_LEN + s)) * HD + 2 * i;

    float inv = powf(10000.f, -(float)(2 * i) / (float)HD);
    float sn, cs;
    sincosf((float)s * inv, &sn, &cs);

    float2 q = *(const float2*)&Q[src];
    float2 k = *(const float2*)&Kk[src];
    float2 v = *(const float2*)&V[src];
    *(float2*)&Qr[dst] = make_float2(q.x * cs - q.y * sn, q.x * sn + q.y * cs);
    *(float2*)&Kr[dst] = make_float2(k.x * cs - k.y * sn, k.x * sn + k.y * cs);
    *(float2*)&Vr[dst] = v;
}

// ================ flash attention, tf32 HMMA ================================
// CTA: 128 threads / 4 warps, 64 queries. Warp = 16 q-rows (m16).
// Per 64-key tile: S = Q@K^T (8 ks x 8 nt mmas), online softmax on C-frags,
// P -> per-warp smem patch (tf32), O += P@V (8 ks x 8 nt mmas).
// Strides chosen bank-conflict-free: K/P stride 68 words, V stride 72 words.
#define AT_KSTR 68
#define AT_VSTR 72
#define AT_SMEM ((64 * AT_KSTR + 64 * AT_VSTR + 4 * 16 * AT_KSTR) * 4)

__global__ __launch_bounds__(128) void attn_mma(
    const float* __restrict__ Qr, const float* __restrict__ Kr,
    const float* __restrict__ Vr, const int* __restrict__ seq_lens,
    float* __restrict__ O)
{
    extern __shared__ uint32_t smw[];
    uint32_t* Ksm = smw;
    uint32_t* Vsm = smw + 64 * AT_KSTR;
    uint32_t* Psm = smw + 64 * AT_KSTR + 64 * AT_VSTR;

    const int tid = threadIdx.x;
    const int warp = tid >> 5, lane = tid & 31;
    const int g = lane >> 2, tg = lane & 3;
    const int qt = blockIdx.x, h = blockIdx.y, b = blockIdx.z;
    const int q0 = qt * 64;
    const int L = seq_lens[b];
    const int bh = b * NH + h;
    const float* Qb = Qr + ((size_t)bh * S_LEN + q0) * HD;
    const float* Kb = Kr + (size_t)bh * S_LEN * HD;
    const float* Vb = Vr + (size_t)bh * S_LEN * HD;

    // stage Q (pre-scaled by 1/8) into Ksm as tf32
#pragma unroll
    for (int j = 0; j < 8; j++) {
        int i = tid + j * 128;
        int r = i >> 4, c = (i & 15) * 4;
        float4 v = *(const float4*)&Qb[(size_t)r * HD + c];
        uint4 u = make_uint4(f2tf32(v.x * 0.125f), f2tf32(v.y * 0.125f),
                             f2tf32(v.z * 0.125f), f2tf32(v.w * 0.125f));
        *(uint4*)&Ksm[r * AT_KSTR + c] = u;
    }
    __syncthreads();

    // register-resident Q A-fragments for the whole kernel
    uint32_t qa[8][4];
    const int mrow = warp * 16;
#pragma unroll
    for (int ks = 0; ks < 8; ks++) {
        qa[ks][0] = Ksm[(mrow + g) * AT_KSTR + 8 * ks + tg];
        qa[ks][1] = Ksm[(mrow + g + 8) * AT_KSTR + 8 * ks + tg];
        qa[ks][2] = Ksm[(mrow + g) * AT_KSTR + 8 * ks + tg + 4];
        qa[ks][3] = Ksm[(mrow + g + 8) * AT_KSTR + 8 * ks + tg + 4];
    }

    float o[8][4];
#pragma unroll
    for (int nt = 0; nt < 8; nt++)
#pragma unroll
        for (int r = 0; r < 4; r++) o[nt][r] = 0.f;
    float m0 = -1e30f, m1 = -1e30f, l0 = 0.f, l1 = 0.f;
    const int qg0 = q0 + mrow + g, qg1 = qg0 + 8;
    const int kmax0 = (qg0 < L) ? L : S_LEN;
    const int kmax1 = (qg1 < L) ? L : S_LEN;

    const int ntiles = (q0 + 63 < L) ? ((L + 63) >> 6) : (S_LEN >> 6);
    uint32_t* Pw = Psm + warp * 16 * AT_KSTR;

    for (int kt = 0; kt < ntiles; kt++) {
        __syncthreads();   // previous tile's smem reads complete
        const float* Kt = Kb + (size_t)kt * 64 * HD;
        const float* Vt = Vb + (size_t)kt * 64 * HD;
#pragma unroll
        for (int j = 0; j < 8; j++) {
            int i = tid + j * 128;
            int r = i >> 4, c = (i & 15) * 4;
            float4 kv = *(const float4*)&Kt[(size_t)r * HD + c];
            float4 vv = *(const float4*)&Vt[(size_t)r * HD + c];
            *(uint4*)&Ksm[r * AT_KSTR + c] =
                make_uint4(f2tf32(kv.x), f2tf32(kv.y), f2tf32(kv.z), f2tf32(kv.w));
            *(uint4*)&Vsm[r * AT_VSTR + c] =
                make_uint4(f2tf32(vv.x), f2tf32(vv.y), f2tf32(vv.z), f2tf32(vv.w));
        }
        __syncthreads();

        // S = Q @ K^T   (scores already scaled via Q)
        float s[8][4];
#pragma unroll
        for (int nt = 0; nt < 8; nt++)
#pragma unroll
            for (int r = 0; r < 4; r++) s[nt][r] = 0.f;
#pragma unroll
        for (int ks = 0; ks < 8; ks++) {
#pragma unroll
            for (int nt = 0; nt < 8; nt++) {
                uint32_t bfr[2];
                bfr[0] = Ksm[(8 * nt + g) * AT_KSTR + 8 * ks + tg];
                bfr[1] = Ksm[(8 * nt + g) * AT_KSTR + 8 * ks + tg + 4];
                mma_tf32(s[nt], qa[ks], bfr);
            }
        }

        // mask (uniform branch per CTA)
        if ((kt + 1) * 64 > L) {
            const int cb = kt * 64 + 2 * tg;
#pragma unroll
            for (int nt = 0; nt < 8; nt++) {
                const int c0 = cb + 8 * nt, c1 = c0 + 1;
                if (c0 >= kmax0) s[nt][0] = -1e30f;
                if (c1 >= kmax0) s[nt][1] = -1e30f;
                if (c0 >= kmax1) s[nt][2] = -1e30f;
                if (c1 >= kmax1) s[nt][3] = -1e30f;
            }
        }

        // online softmax (rows g -> regs 0,1 ; rows g+8 -> regs 2,3)
        float mx0 = -1e30f, mx1 = -1e30f;
#pragma unroll
        for (int nt = 0; nt < 8; nt++) {
            mx0 = fmaxf(mx0, fmaxf(s[nt][0], s[nt][1]));
            mx1 = fmaxf(mx1, fmaxf(s[nt][2], s[nt][3]));
        }
        mx0 = fmaxf(mx0, __shfl_xor_sync(0xffffffffu, mx0, 1));
        mx0 = fmaxf(mx0, __shfl_xor_sync(0xffffffffu, mx0, 2));
        mx1 = fmaxf(mx1, __shfl_xor_sync(0xffffffffu, mx1, 1));
        mx1 = fmaxf(mx1, __shfl_xor_sync(0xffffffffu, mx1, 2));
        const float mn0 = fmaxf(m0, mx0), mn1 = fmaxf(m1, mx1);
        const float a0 = __expf(m0 - mn0), a1 = __expf(m1 - mn1);
        float ls0 = 0.f, ls1 = 0.f;
#pragma unroll
        for (int nt = 0; nt < 8; nt++) {
            s[nt][0] = __expf(s[nt][0] - mn0); ls0 += s[nt][0];
            s[nt][1] = __expf(s[nt][1] - mn0); ls0 += s[nt][1];
            s[nt][2] = __expf(s[nt][2] - mn1); ls1 += s[nt][2];
            s[nt][3] = __expf(s[nt][3] - mn1); ls1 += s[nt][3];
        }
        ls0 += __shfl_xor_sync(0xffffffffu, ls0, 1);
        ls0 += __shfl_xor_sync(0xffffffffu, ls0, 2);
        ls1 += __shfl_xor_sync(0xffffffffu, ls1, 1);
        ls1 += __shfl_xor_sync(0xffffffffu, ls1, 2);
        l0 = l0 * a0 + ls0;  l1 = l1 * a1 + ls1;
        m0 = mn0;  m1 = mn1;
#pragma unroll
        for (int nt = 0; nt < 8; nt++) {
            o[nt][0] *= a0; o[nt][1] *= a0;
            o[nt][2] *= a1; o[nt][3] *= a1;
        }

        // P (C-layout) -> per-warp smem patch as tf32 (A-layout reload)
#pragma unroll
        for (int nt = 0; nt < 8; nt++) {
            const int cc = 8 * nt + 2 * tg;
            Pw[g * AT_KSTR + cc]           = f2tf32(s[nt][0]);
            Pw[g * AT_KSTR + cc + 1]       = f2tf32(s[nt][1]);
            Pw[(g + 8) * AT_KSTR + cc]     = f2tf32(s[nt][2]);
            Pw[(g + 8) * AT_KSTR + cc + 1] = f2tf32(s[nt][3]);
        }
        __syncwarp();

        // O += P @ V
#pragma unroll
        for (int ks = 0; ks < 8; ks++) {
            uint32_t pa[4];
            pa[0] = Pw[g * AT_KSTR + 8 * ks + tg];
            pa[1] = Pw[(g + 8) * AT_KSTR + 8 * ks + tg];
            pa[2] = Pw[g * AT_KSTR + 8 * ks + tg + 4];
            pa[3] = Pw[(g + 8) * AT_KSTR + 8 * ks + tg + 4];
#pragma unroll
            for (int nt = 0; nt < 8; nt++) {
                uint32_t vb[2];
                vb[0] = Vsm[(8 * ks + tg) * AT_VSTR + 8 * nt + g];
                vb[1] = Vsm[(8 * ks + tg + 4) * AT_VSTR + 8 * nt + g];
                mma_tf32(o[nt], pa, vb);
            }
        }
        __syncwarp();   // PV reads done before next tile's P stores
    }

    // epilogue: normalize and write [b, s, h*d]
    const float i0 = 1.f / l0, i1 = 1.f / l1;
    float* d0 = O + ((size_t)b * S_LEN + qg0) * DIM + h * HD;
    float* d1 = O + ((size_t)b * S_LEN + qg1) * DIM + h * HD;
#pragma unroll
    for (int nt = 0; nt < 8; nt++) {
        const int cc = 8 * nt + 2 * tg;
        *(float2*)&d0[cc] = make_float2(o[nt][0] * i0, o[nt][1] * i0);
        *(float2*)&d1[cc] = make_float2(o[nt][2] * i1, o[nt][3] * i1);
    }
}

// ---------------- launch -----------------------------------------------------
extern "C" void kernel_launch(void* const* d_in, const int* in_sizes, int n_in,
                              void* d_out, int out_size)
{
    const float* x   = (const float*)d_in[0];
    const int*   seq = (const int*)  d_in[1];
    const float* wq  = (const float*)d_in[2];
    const float* wk  = (const float*)d_in[3];
    const float* wv  = (const float*)d_in[4];
    const float* wo  = (const float*)d_in[5];
    float* out = (float*)d_out;

    float *Qp, *Kp, *Vp, *Qr, *Kr, *Vr, *Oa;
    cudaGetSymbolAddress((void**)&Qp, g_Qp);
    cudaGetSymbolAddress((void**)&Kp, g_Kp);
    cudaGetSymbolAddress((void**)&Vp, g_Vp);
    cudaGetSymbolAddress((void**)&Qr, g_Qr);
    cudaGetSymbolAddress((void**)&Kr, g_Kr);
    cudaGetSymbolAddress((void**)&Vr, g_Vr);
    cudaGetSymbolAddress((void**)&Oa, g_O);

    cudaFuncSetAttribute(gemm_mma,
                         cudaFuncAttributeMaxDynamicSharedMemorySize, G_SMEM_TOTAL);
    cudaFuncSetAttribute(attn_mma,
                         cudaFuncAttributeMaxDynamicSharedMemorySize, AT_SMEM);

    dim3 gg(DIM / 128, MROWS / 128);
    gemm_mma<<<gg, 256, G_SMEM_TOTAL>>>(x, wq, Qp);
    gemm_mma<<<gg, 256, G_SMEM_TOTAL>>>(x, wk, Kp);
    gemm_mma<<<gg, 256, G_SMEM_TOTAL>>>(x, wv, Vp);

    rope_reshape<<<(B_SZ * S_LEN * NH * 32) / 256, 256>>>(Qp, Kp, Vp, Qr, Kr, Vr);

    attn_mma<<<dim3(S_LEN / 64, NH, B_SZ), 128, AT_SMEM>>>(Qr, Kr, Vr, seq, Oa);

    gemm_mma<<<gg, 256, G_SMEM_TOTAL>>>(Oa, wo, out);
}

// round 9
// speedup vs baseline: 3.5237x; 1.0110x over previous
#include <cuda_runtime.h>
#include <math.h>
#include <stdint.h>

#define B_SZ   4
#define S_LEN  2048
#define DIM    1024
#define NH     16
#define HD     64
#define MROWS  (B_SZ * S_LEN)   /* 8192 */

// ---------------- scratch (device globals: no allocation allowed) -----------
__device__ float    g_Qp[MROWS * DIM];      // fp32 projections
__device__ float    g_Kp[MROWS * DIM];
__device__ float    g_Vp[MROWS * DIM];
__device__ uint32_t g_Qr[MROWS * DIM];      // tf32 bit patterns, [bh,s,d]
__device__ uint32_t g_Kr[MROWS * DIM];
__device__ uint32_t g_Vr[MROWS * DIM];
__device__ uint32_t g_O [MROWS * DIM];      // attention out, tf32 patterns
__device__ uint32_t g_xt[MROWS * DIM];      // x as tf32
__device__ uint32_t g_wqt[DIM * DIM];       // weights as tf32
__device__ uint32_t g_wkt[DIM * DIM];
__device__ uint32_t g_wvt[DIM * DIM];
__device__ uint32_t g_wot[DIM * DIM];

// ======================= helpers ============================================
__device__ __forceinline__ uint32_t f2tf32(float x) {
    uint32_t u;
    asm("cvt.rna.tf32.f32 %0, %1;" : "=r"(u) : "f"(x));
    return u;
}

// D += A@B via m16n8k8 tf32 HMMA (fp32 accum).
__device__ __forceinline__ void mma_tf32(
    float* d, const uint32_t* a, const uint32_t* b)
{
    asm volatile(
        "mma.sync.aligned.m16n8k8.row.col.f32.tf32.tf32.f32 "
        "{%0,%1,%2,%3}, {%4,%5,%6,%7}, {%8,%9}, {%0,%1,%2,%3};"
        : "+f"(d[0]), "+f"(d[1]), "+f"(d[2]), "+f"(d[3])
        : "r"(a[0]), "r"(a[1]), "r"(a[2]), "r"(a[3]),
          "r"(b[0]), "r"(b[1]));
}

// ---------------- fp32 -> tf32 prepass (bandwidth bound) --------------------
__global__ __launch_bounds__(256) void cvt_tf32(
    const float* __restrict__ in, uint32_t* __restrict__ out)
{
    int i = (blockIdx.x * blockDim.x + threadIdx.x) * 4;
    float4 v = *(const float4*)&in[i];
    *(uint4*)&out[i] = make_uint4(f2tf32(v.x), f2tf32(v.y),
                                  f2tf32(v.z), f2tf32(v.w));
}

// ============ tf32 HMMA GEMM: C[m][n] = sum_k A[m][k] * B[n][k] =============
// Inputs pre-converted to tf32 bit patterns. BM=BN=128, BK=32, 256 threads.
#define GBK      32
#define GSTRIDE  36
#define GTILE    (128 * GSTRIDE)
#define G_SMEM_TOTAL (4 * GTILE * 4)

__global__ __launch_bounds__(256) void gemm_mma(
    const uint32_t* __restrict__ A, const uint32_t* __restrict__ B,
    float* __restrict__ C)
{
    extern __shared__ uint32_t smw[];
    uint32_t* As = smw;
    uint32_t* Bs = smw + 2 * GTILE;

    const int tid  = threadIdx.x, wid = tid >> 5, lane = tid & 31;
    const int wm   = wid & 1;
    const int wn   = wid >> 1;
    const int g    = lane >> 2;
    const int tg   = lane & 3;
    const int ntile = blockIdx.x, mtile = blockIdx.y;
    const int K = DIM, N = DIM;
    const uint32_t* Ag = A + (size_t)mtile * 128 * K;
    const uint32_t* Bg = B + (size_t)ntile * 128 * K;

    float acc[4][4][4];
#pragma unroll
    for (int mt = 0; mt < 4; mt++)
#pragma unroll
        for (int nt = 0; nt < 4; nt++)
#pragma unroll
            for (int r = 0; r < 4; r++) acc[mt][nt][r] = 0.f;

    uint4 ra[4], rb[4];

#define G_LDG(it) do {                                                         \
    const int _k0 = (it) * GBK;                                                \
    _Pragma("unroll")                                                          \
    for (int j = 0; j < 4; j++) {                                              \
        int i = tid + j * 256;                                                 \
        int r = i >> 3, c = i & 7;                                             \
        ra[j] = *(const uint4*)&Ag[(size_t)r * K + _k0 + c * 4];               \
        rb[j] = *(const uint4*)&Bg[(size_t)r * K + _k0 + c * 4];               \
    }                                                                          \
} while (0)

#define G_STS(st) do {                                                         \
    uint32_t* _pa = As + (st) * GTILE;                                         \
    uint32_t* _pb = Bs + (st) * GTILE;                                         \
    _Pragma("unroll")                                                          \
    for (int j = 0; j < 4; j++) {                                              \
        int i = tid + j * 256;                                                 \
        int r = i >> 3, c = i & 7;                                             \
        *(uint4*)&_pa[r * GSTRIDE + c * 4] = ra[j];                            \
        *(uint4*)&_pb[r * GSTRIDE + c * 4] = rb[j];                            \
    }                                                                          \
} while (0)

    const int niters = K / GBK;
    G_LDG(0);
    G_STS(0);
    __syncthreads();

    for (int it = 0; it < niters; it++) {
        const int st = it & 1;
        if (it + 1 < niters) G_LDG(it + 1);

        const uint32_t* pa = As + st * GTILE;
        const uint32_t* pb = Bs + st * GTILE;
#pragma unroll
        for (int ks = 0; ks < 4; ks++) {
            const int kk = ks * 8;
            uint32_t af[4][4], bf[4][2];
#pragma unroll
            for (int mt = 0; mt < 4; mt++) {
                const int row = wm * 64 + mt * 16;
                af[mt][0] = pa[(row + g)     * GSTRIDE + kk + tg];
                af[mt][1] = pa[(row + g + 8) * GSTRIDE + kk + tg];
                af[mt][2] = pa[(row + g)     * GSTRIDE + kk + tg + 4];
                af[mt][3] = pa[(row + g + 8) * GSTRIDE + kk + tg + 4];
            }
#pragma unroll
            for (int nt = 0; nt < 4; nt++) {
                const int col = wn * 32 + nt * 8;
                bf[nt][0] = pb[(col + g) * GSTRIDE + kk + tg];
                bf[nt][1] = pb[(col + g) * GSTRIDE + kk + tg + 4];
            }
#pragma unroll
            for (int mt = 0; mt < 4; mt++)
#pragma unroll
                for (int nt = 0; nt < 4; nt++)
                    mma_tf32(acc[mt][nt], af[mt], bf[nt]);
        }

        if (it + 1 < niters) G_STS((it + 1) & 1);
        __syncthreads();
    }

#pragma unroll
    for (int mt = 0; mt < 4; mt++) {
        const int row = mtile * 128 + wm * 64 + mt * 16 + g;
#pragma unroll
        for (int nt = 0; nt < 4; nt++) {
            const int col = ntile * 128 + wn * 32 + nt * 8 + 2 * tg;
            *(float2*)&C[(size_t)row * N + col] =
                make_float2(acc[mt][nt][0], acc[mt][nt][1]);
            *(float2*)&C[(size_t)(row + 8) * N + col] =
                make_float2(acc[mt][nt][2], acc[mt][nt][3]);
        }
    }
}

// ------------- RoPE + reshape; outputs tf32 patterns (Q pre-scaled 1/8) -----
__global__ __launch_bounds__(256) void rope_reshape(
    const float* __restrict__ Q, const float* __restrict__ Kk,
    const float* __restrict__ V,
    uint32_t* __restrict__ Qr, uint32_t* __restrict__ Kr,
    uint32_t* __restrict__ Vr)
{
    int idx = blockIdx.x * blockDim.x + threadIdx.x;
    int i = idx & 31;
    int h = (idx >> 5) & 15;
    int s = (idx >> 9) & 2047;
    int b = idx >> 20;

    size_t src = ((size_t)(b * S_LEN + s)) * DIM + h * HD + 2 * i;
    size_t dst = ((size_t)((b * NH + h) * S_LEN + s)) * HD + 2 * i;

    float inv = powf(10000.f, -(float)(2 * i) / (float)HD);
    float sn, cs;
    sincosf((float)s * inv, &sn, &cs);

    float2 q = *(const float2*)&Q[src];
    float2 k = *(const float2*)&Kk[src];
    float2 v = *(const float2*)&V[src];
    float qr = (q.x * cs - q.y * sn) * 0.125f;
    float qi = (q.x * sn + q.y * cs) * 0.125f;
    *(uint2*)&Qr[dst] = make_uint2(f2tf32(qr), f2tf32(qi));
    *(uint2*)&Kr[dst] = make_uint2(f2tf32(k.x * cs - k.y * sn),
                                   f2tf32(k.x * sn + k.y * cs));
    *(uint2*)&Vr[dst] = make_uint2(f2tf32(v.x), f2tf32(v.y));
}

// ================ flash attention, tf32 HMMA (inputs pre-tf32) ==============
#define AT_KSTR 68
#define AT_VSTR 72
#define AT_SMEM ((64 * AT_KSTR + 64 * AT_VSTR + 4 * 16 * AT_KSTR) * 4)

__global__ __launch_bounds__(128) void attn_mma(
    const uint32_t* __restrict__ Qr, const uint32_t* __restrict__ Kr,
    const uint32_t* __restrict__ Vr, const int* __restrict__ seq_lens,
    uint32_t* __restrict__ O)
{
    extern __shared__ uint32_t smw[];
    uint32_t* Ksm = smw;
    uint32_t* Vsm = smw + 64 * AT_KSTR;
    uint32_t* Psm = smw + 64 * AT_KSTR + 64 * AT_VSTR;

    const int tid = threadIdx.x;
    const int warp = tid >> 5, lane = tid & 31;
    const int g = lane >> 2, tg = lane & 3;
    const int qt = blockIdx.x, h = blockIdx.y, b = blockIdx.z;
    const int q0 = qt * 64;
    const int L = seq_lens[b];
    const int bh = b * NH + h;
    const uint32_t* Qb = Qr + ((size_t)bh * S_LEN + q0) * HD;
    const uint32_t* Kb = Kr + (size_t)bh * S_LEN * HD;
    const uint32_t* Vb = Vr + (size_t)bh * S_LEN * HD;

    // stage Q (already tf32, pre-scaled) into Ksm
#pragma unroll
    for (int j = 0; j < 8; j++) {
        int i = tid + j * 128;
        int r = i >> 4, c = (i & 15) * 4;
        *(uint4*)&Ksm[r * AT_KSTR + c] = *(const uint4*)&Qb[(size_t)r * HD + c];
    }
    __syncthreads();

    // register-resident Q A-fragments
    uint32_t qa[8][4];
    const int mrow = warp * 16;
#pragma unroll
    for (int ks = 0; ks < 8; ks++) {
        qa[ks][0] = Ksm[(mrow + g) * AT_KSTR + 8 * ks + tg];
        qa[ks][1] = Ksm[(mrow + g + 8) * AT_KSTR + 8 * ks + tg];
        qa[ks][2] = Ksm[(mrow + g) * AT_KSTR + 8 * ks + tg + 4];
        qa[ks][3] = Ksm[(mrow + g + 8) * AT_KSTR + 8 * ks + tg + 4];
    }

    float o[8][4];
#pragma unroll
    for (int nt = 0; nt < 8; nt++)
#pragma unroll
        for (int r = 0; r < 4; r++) o[nt][r] = 0.f;
    float m0 = -1e30f, m1 = -1e30f, l0 = 0.f, l1 = 0.f;
    const int qg0 = q0 + mrow + g, qg1 = qg0 + 8;
    const int kmax0 = (qg0 < L) ? L : S_LEN;
    const int kmax1 = (qg1 < L) ? L : S_LEN;

    const int ntiles = (q0 + 63 < L) ? ((L + 63) >> 6) : (S_LEN >> 6);
    uint32_t* Pw = Psm + warp * 16 * AT_KSTR;

    for (int kt = 0; kt < ntiles; kt++) {
        __syncthreads();
        const uint32_t* Kt = Kb + (size_t)kt * 64 * HD;
        const uint32_t* Vt = Vb + (size_t)kt * 64 * HD;
#pragma unroll
        for (int j = 0; j < 8; j++) {
            int i = tid + j * 128;
            int r = i >> 4, c = (i & 15) * 4;
            *(uint4*)&Ksm[r * AT_KSTR + c] = *(const uint4*)&Kt[(size_t)r * HD + c];
            *(uint4*)&Vsm[r * AT_VSTR + c] = *(const uint4*)&Vt[(size_t)r * HD + c];
        }
        __syncthreads();

        // S = Q @ K^T
        float s[8][4];
#pragma unroll
        for (int nt = 0; nt < 8; nt++)
#pragma unroll
            for (int r = 0; r < 4; r++) s[nt][r] = 0.f;
#pragma unroll
        for (int ks = 0; ks < 8; ks++) {
#pragma unroll
            for (int nt = 0; nt < 8; nt++) {
                uint32_t bfr[2];
                bfr[0] = Ksm[(8 * nt + g) * AT_KSTR + 8 * ks + tg];
                bfr[1] = Ksm[(8 * nt + g) * AT_KSTR + 8 * ks + tg + 4];
                mma_tf32(s[nt], qa[ks], bfr);
            }
        }

        // mask
        if ((kt + 1) * 64 > L) {
            const int cb = kt * 64 + 2 * tg;
#pragma unroll
            for (int nt = 0; nt < 8; nt++) {
                const int c0 = cb + 8 * nt, c1 = c0 + 1;
                if (c0 >= kmax0) s[nt][0] = -1e30f;
                if (c1 >= kmax0) s[nt][1] = -1e30f;
                if (c0 >= kmax1) s[nt][2] = -1e30f;
                if (c1 >= kmax1) s[nt][3] = -1e30f;
            }
        }

        // online softmax
        float mx0 = -1e30f, mx1 = -1e30f;
#pragma unroll
        for (int nt = 0; nt < 8; nt++) {
            mx0 = fmaxf(mx0, fmaxf(s[nt][0], s[nt][1]));
            mx1 = fmaxf(mx1, fmaxf(s[nt][2], s[nt][3]));
        }
        mx0 = fmaxf(mx0, __shfl_xor_sync(0xffffffffu, mx0, 1));
        mx0 = fmaxf(mx0, __shfl_xor_sync(0xffffffffu, mx0, 2));
        mx1 = fmaxf(mx1, __shfl_xor_sync(0xffffffffu, mx1, 1));
        mx1 = fmaxf(mx1, __shfl_xor_sync(0xffffffffu, mx1, 2));
        const float mn0 = fmaxf(m0, mx0), mn1 = fmaxf(m1, mx1);
        const float a0 = __expf(m0 - mn0), a1 = __expf(m1 - mn1);
        float ls0 = 0.f, ls1 = 0.f;
#pragma unroll
        for (int nt = 0; nt < 8; nt++) {
            s[nt][0] = __expf(s[nt][0] - mn0); ls0 += s[nt][0];
            s[nt][1] = __expf(s[nt][1] - mn0); ls0 += s[nt][1];
            s[nt][2] = __expf(s[nt][2] - mn1); ls1 += s[nt][2];
            s[nt][3] = __expf(s[nt][3] - mn1); ls1 += s[nt][3];
        }
        ls0 += __shfl_xor_sync(0xffffffffu, ls0, 1);
        ls0 += __shfl_xor_sync(0xffffffffu, ls0, 2);
        ls1 += __shfl_xor_sync(0xffffffffu, ls1, 1);
        ls1 += __shfl_xor_sync(0xffffffffu, ls1, 2);
        l0 = l0 * a0 + ls0;  l1 = l1 * a1 + ls1;
        m0 = mn0;  m1 = mn1;
#pragma unroll
        for (int nt = 0; nt < 8; nt++) {
            o[nt][0] *= a0; o[nt][1] *= a0;
            o[nt][2] *= a1; o[nt][3] *= a1;
        }

        // P -> per-warp smem patch (tf32)
#pragma unroll
        for (int nt = 0; nt < 8; nt++) {
            const int cc = 8 * nt + 2 * tg;
            Pw[g * AT_KSTR + cc]           = f2tf32(s[nt][0]);
            Pw[g * AT_KSTR + cc + 1]       = f2tf32(s[nt][1]);
            Pw[(g + 8) * AT_KSTR + cc]     = f2tf32(s[nt][2]);
            Pw[(g + 8) * AT_KSTR + cc + 1] = f2tf32(s[nt][3]);
        }
        __syncwarp();

        // O += P @ V
#pragma unroll
        for (int ks = 0; ks < 8; ks++) {
            uint32_t pa[4];
            pa[0] = Pw[g * AT_KSTR + 8 * ks + tg];
            pa[1] = Pw[(g + 8) * AT_KSTR + 8 * ks + tg];
            pa[2] = Pw[g * AT_KSTR + 8 * ks + tg + 4];
            pa[3] = Pw[(g + 8) * AT_KSTR + 8 * ks + tg + 4];
#pragma unroll
            for (int nt = 0; nt < 8; nt++) {
                uint32_t vb[2];
                vb[0] = Vsm[(8 * ks + tg) * AT_VSTR + 8 * nt + g];
                vb[1] = Vsm[(8 * ks + tg + 4) * AT_VSTR + 8 * nt + g];
                mma_tf32(o[nt], pa, vb);
            }
        }
        __syncwarp();
    }

    // epilogue: normalize, write as tf32 patterns (consumed by WO gemm)
    const float i0 = 1.f / l0, i1 = 1.f / l1;
    uint32_t* d0 = O + ((size_t)b * S_LEN + qg0) * DIM + h * HD;
    uint32_t* d1 = O + ((size_t)b * S_LEN + qg1) * DIM + h * HD;
#pragma unroll
    for (int nt = 0; nt < 8; nt++) {
        const int cc = 8 * nt + 2 * tg;
        *(uint2*)&d0[cc] = make_uint2(f2tf32(o[nt][0] * i0), f2tf32(o[nt][1] * i0));
        *(uint2*)&d1[cc] = make_uint2(f2tf32(o[nt][2] * i1), f2tf32(o[nt][3] * i1));
    }
}

// ---------------- launch -----------------------------------------------------
extern "C" void kernel_launch(void* const* d_in, const int* in_sizes, int n_in,
                              void* d_out, int out_size)
{
    const float* x   = (const float*)d_in[0];
    const int*   seq = (const int*)  d_in[1];
    const float* wq  = (const float*)d_in[2];
    const float* wk  = (const float*)d_in[3];
    const float* wv  = (const float*)d_in[4];
    const float* wo  = (const float*)d_in[5];
    float* out = (float*)d_out;

    float *Qp, *Kp, *Vp;
    uint32_t *Qr, *Kr, *Vr, *Oa, *xt, *wqt, *wkt, *wvt, *wot;
    cudaGetSymbolAddress((void**)&Qp, g_Qp);
    cudaGetSymbolAddress((void**)&Kp, g_Kp);
    cudaGetSymbolAddress((void**)&Vp, g_Vp);
    cudaGetSymbolAddress((void**)&Qr, g_Qr);
    cudaGetSymbolAddress((void**)&Kr, g_Kr);
    cudaGetSymbolAddress((void**)&Vr, g_Vr);
    cudaGetSymbolAddress((void**)&Oa, g_O);
    cudaGetSymbolAddress((void**)&xt, g_xt);
    cudaGetSymbolAddress((void**)&wqt, g_wqt);
    cudaGetSymbolAddress((void**)&wkt, g_wkt);
    cudaGetSymbolAddress((void**)&wvt, g_wvt);
    cudaGetSymbolAddress((void**)&wot, g_wot);

    cudaFuncSetAttribute(gemm_mma,
                         cudaFuncAttributeMaxDynamicSharedMemorySize, G_SMEM_TOTAL);
    cudaFuncSetAttribute(attn_mma,
                         cudaFuncAttributeMaxDynamicSharedMemorySize, AT_SMEM);

    // prepass: convert x + weights to tf32
    cvt_tf32<<<(MROWS * DIM) / 1024, 256>>>(x, xt);
    cvt_tf32<<<(DIM * DIM) / 1024, 256>>>(wq, wqt);
    cvt_tf32<<<(DIM * DIM) / 1024, 256>>>(wk, wkt);
    cvt_tf32<<<(DIM * DIM) / 1024, 256>>>(wv, wvt);
    cvt_tf32<<<(DIM * DIM) / 1024, 256>>>(wo, wot);

    dim3 gg(DIM / 128, MROWS / 128);
    gemm_mma<<<gg, 256, G_SMEM_TOTAL>>>(xt, wqt, Qp);
    gemm_mma<<<gg, 256, G_SMEM_TOTAL>>>(xt, wkt, Kp);
    gemm_mma<<<gg, 256, G_SMEM_TOTAL>>>(xt, wvt, Vp);

    rope_reshape<<<(B_SZ * S_LEN * NH * 32) / 256, 256>>>(Qp, Kp, Vp, Qr, Kr, Vr);

    attn_mma<<<dim3(S_LEN / 64, NH, B_SZ), 128, AT_SMEM>>>(Qr, Kr, Vr, seq, Oa);

    gemm_mma<<<gg, 256, G_SMEM_TOTAL>>>(Oa, wot, out);
}

// round 16
// speedup vs baseline: 3.7722x; 1.0705x over previous
#include <cuda_runtime.h>
#include <math.h>
#include <stdint.h>

#define B_SZ   4
#define S_LEN  2048
#define DIM    1024
#define NH     16
#define HD     64
#define MROWS  (B_SZ * S_LEN)   /* 8192 */

// ---------------- scratch (device globals: no allocation allowed) -----------
__device__ float    g_Qp[MROWS * DIM];      // fp32 projections
__device__ float    g_Kp[MROWS * DIM];
__device__ float    g_Vp[MROWS * DIM];
__device__ uint32_t g_Qr[MROWS * DIM];      // tf32 bit patterns, [bh,s,d]
__device__ uint32_t g_Kr[MROWS * DIM];
__device__ uint32_t g_Vr[MROWS * DIM];
__device__ uint32_t g_O [MROWS * DIM];      // attention out, tf32 patterns
__device__ uint32_t g_xt[MROWS * DIM];      // x as tf32
__device__ uint32_t g_wqt[DIM * DIM];       // weights as tf32
__device__ uint32_t g_wkt[DIM * DIM];
__device__ uint32_t g_wvt[DIM * DIM];
__device__ uint32_t g_wot[DIM * DIM];

// ======================= helpers ============================================
__device__ __forceinline__ uint32_t f2tf32(float x) {
    uint32_t u;
    asm("cvt.rna.tf32.f32 %0, %1;" : "=r"(u) : "f"(x));
    return u;
}

// D += A@B via m16n8k8 tf32 HMMA (fp32 accum).
__device__ __forceinline__ void mma_tf32(
    float* d, const uint32_t* a, const uint32_t* b)
{
    asm volatile(
        "mma.sync.aligned.m16n8k8.row.col.f32.tf32.tf32.f32 "
        "{%0,%1,%2,%3}, {%4,%5,%6,%7}, {%8,%9}, {%0,%1,%2,%3};"
        : "+f"(d[0]), "+f"(d[1]), "+f"(d[2]), "+f"(d[3])
        : "r"(a[0]), "r"(a[1]), "r"(a[2]), "r"(a[3]),
          "r"(b[0]), "r"(b[1]));
}

__device__ __forceinline__ void cp16(uint32_t dst_smem, const void* src) {
    asm volatile("cp.async.cg.shared.global [%0], [%1], 16;"
                 :: "r"(dst_smem), "l"(src));
}
#define CP_COMMIT() asm volatile("cp.async.commit_group;" ::: "memory")
#define CP_WAIT1()  asm volatile("cp.async.wait_group 1;" ::: "memory")
#define CP_WAIT0()  asm volatile("cp.async.wait_group 0;" ::: "memory")

// ---------------- fp32 -> tf32 prepass (bandwidth bound) --------------------
__global__ __launch_bounds__(256) void cvt_tf32(
    const float* __restrict__ in, uint32_t* __restrict__ out)
{
    int i = (blockIdx.x * blockDim.x + threadIdx.x) * 4;
    float4 v = *(const float4*)&in[i];
    *(uint4*)&out[i] = make_uint4(f2tf32(v.x), f2tf32(v.y),
                                  f2tf32(v.z), f2tf32(v.w));
}

// ============ tf32 HMMA GEMM, cp.async 3-stage pipeline =====================
// C[m][n] = sum_k A[m][k] * B[n][k]. BM=BN=128, BK=32, 256 threads,
// 8 warps (2m x 4n), warp tile 64x32. grid.z selects (B, C) operand pair.
#define GBK      32
#define GSTRIDE  36                      /* words per smem row */
#define GTILE    (128 * GSTRIDE)         /* words per operand per stage */
#define G_NSTG   3
#define G_SMEM_TOTAL (G_NSTG * 2 * GTILE * 4)   /* 110592 B */
#define G_KITERS (DIM / GBK)             /* 32 */

__global__ __launch_bounds__(256, 2) void qkv_gemm(
    const uint32_t* __restrict__ A,
    const uint32_t* __restrict__ B0, const uint32_t* __restrict__ B1,
    const uint32_t* __restrict__ B2,
    float* __restrict__ C0, float* __restrict__ C1, float* __restrict__ C2)
{
    extern __shared__ uint32_t smw[];

    const int tid  = threadIdx.x, wid = tid >> 5, lane = tid & 31;
    const int wm   = wid & 1;
    const int wn   = wid >> 1;
    const int g    = lane >> 2;
    const int tg   = lane & 3;
    const int ntile = blockIdx.x, mtile = blockIdx.y, zz = blockIdx.z;
    const int K = DIM, N = DIM;

    const uint32_t* Bsel = (zz == 0) ? B0 : (zz == 1) ? B1 : B2;
    float*          Csel = (zz == 0) ? C0 : (zz == 1) ? C1 : C2;
    const uint32_t* Ag = A    + (size_t)mtile * 128 * K;
    const uint32_t* Bg = Bsel + (size_t)ntile * 128 * K;

    const uint32_t smem_u = (uint32_t)__cvta_generic_to_shared(smw);
    const int r_ld = tid >> 3, c_ld = tid & 7;   // 32 rows x 8 cols of 16B

    float acc[4][4][4];
#pragma unroll
    for (int mt = 0; mt < 4; mt++)
#pragma unroll
        for (int nt = 0; nt < 4; nt++)
#pragma unroll
            for (int r = 0; r < 4; r++) acc[mt][nt][r] = 0.f;

    // issue one stage: A tile + B tile (128x32 each), 4 rows-of-32 per op
#define G_ISSUE(st, it) do {                                                   \
    const int _k0 = (it) * GBK;                                                \
    uint32_t _sa = smem_u + ((st) * 2 * GTILE) * 4;                            \
    uint32_t _sb = _sa + GTILE * 4;                                            \
    _Pragma("unroll")                                                          \
    for (int j = 0; j < 4; j++) {                                              \
        int r = r_ld + j * 32;                                                 \
        uint32_t off = (r * GSTRIDE + c_ld * 4) * 4;                           \
        cp16(_sa + off, &Ag[(size_t)r * K + _k0 + c_ld * 4]);                  \
        cp16(_sb + off, &Bg[(size_t)r * K + _k0 + c_ld * 4]);                  \
    }                                                                          \
    CP_COMMIT();                                                               \
} while (0)

    G_ISSUE(0, 0);
    G_ISSUE(1, 1);
    CP_WAIT1();
    __syncthreads();

    for (int it = 0; it < G_KITERS; it++) {
        const int st = it % G_NSTG;
        const uint32_t* pa = smw + st * 2 * GTILE;
        const uint32_t* pb = pa + GTILE;

#pragma unroll
        for (int ks = 0; ks < 4; ks++) {
            const int kk = ks * 8;
            uint32_t af[4][4], bf[4][2];
#pragma unroll
            for (int mt = 0; mt < 4; mt++) {
                const int row = wm * 64 + mt * 16;
                af[mt][0] = pa[(row + g)     * GSTRIDE + kk + tg];
                af[mt][1] = pa[(row + g + 8) * GSTRIDE + kk + tg];
                af[mt][2] = pa[(row + g)     * GSTRIDE + kk + tg + 4];
                af[mt][3] = pa[(row + g + 8) * GSTRIDE + kk + tg + 4];
            }
#pragma unroll
            for (int nt = 0; nt < 4; nt++) {
                const int col = wn * 32 + nt * 8;
                bf[nt][0] = pb[(col + g) * GSTRIDE + kk + tg];
                bf[nt][1] = pb[(col + g) * GSTRIDE + kk + tg + 4];
            }
#pragma unroll
            for (int mt = 0; mt < 4; mt++)
#pragma unroll
                for (int nt = 0; nt < 4; nt++)
                    mma_tf32(acc[mt][nt], af[mt], bf[nt]);
        }

        if (it + 2 < G_KITERS) {
            G_ISSUE((it + 2) % G_NSTG, it + 2);
            CP_WAIT1();
        } else {
            CP_WAIT0();
        }
        __syncthreads();
    }

    // epilogue
#pragma unroll
    for (int mt = 0; mt < 4; mt++) {
        const int row = mtile * 128 + wm * 64 + mt * 16 + g;
#pragma unroll
        for (int nt = 0; nt < 4; nt++) {
            const int col = ntile * 128 + wn * 32 + nt * 8 + 2 * tg;
            *(float2*)&Csel[(size_t)row * N + col] =
                make_float2(acc[mt][nt][0], acc[mt][nt][1]);
            *(float2*)&Csel[(size_t)(row + 8) * N + col] =
                make_float2(acc[mt][nt][2], acc[mt][nt][3]);
        }
    }
}

// ------------- RoPE + reshape; outputs tf32 patterns (Q pre-scaled 1/8) -----
__global__ __launch_bounds__(256) void rope_reshape(
    const float* __restrict__ Q, const float* __restrict__ Kk,
    const float* __restrict__ V,
    uint32_t* __restrict__ Qr, uint32_t* __restrict__ Kr,
    uint32_t* __restrict__ Vr)
{
    int idx = blockIdx.x * blockDim.x + threadIdx.x;
    int i = idx & 31;
    int h = (idx >> 5) & 15;
    int s = (idx >> 9) & 2047;
    int b = idx >> 20;

    size_t src = ((size_t)(b * S_LEN + s)) * DIM + h * HD + 2 * i;
    size_t dst = ((size_t)((b * NH + h) * S_LEN + s)) * HD + 2 * i;

    float inv = powf(10000.f, -(float)(2 * i) / (float)HD);
    float sn, cs;
    sincosf((float)s * inv, &sn, &cs);

    float2 q = *(const float2*)&Q[src];
    float2 k = *(const float2*)&Kk[src];
    float2 v = *(const float2*)&V[src];
    float qr = (q.x * cs - q.y * sn) * 0.125f;
    float qi = (q.x * sn + q.y * cs) * 0.125f;
    *(uint2*)&Qr[dst] = make_uint2(f2tf32(qr), f2tf32(qi));
    *(uint2*)&Kr[dst] = make_uint2(f2tf32(k.x * cs - k.y * sn),
                                   f2tf32(k.x * sn + k.y * cs));
    *(uint2*)&Vr[dst] = make_uint2(f2tf32(v.x), f2tf32(v.y));
}

// ================ flash attention, tf32 HMMA (inputs pre-tf32) ==============
#define AT_KSTR 68
#define AT_VSTR 72
#define AT_SMEM ((64 * AT_KSTR + 64 * AT_VSTR + 4 * 16 * AT_KSTR) * 4)

__global__ __launch_bounds__(128) void attn_mma(
    const uint32_t* __restrict__ Qr, const uint32_t* __restrict__ Kr,
    const uint32_t* __restrict__ Vr, const int* __restrict__ seq_lens,
    uint32_t* __restrict__ O)
{
    extern __shared__ uint32_t smw[];
    uint32_t* Ksm = smw;
    uint32_t* Vsm = smw + 64 * AT_KSTR;
    uint32_t* Psm = smw + 64 * AT_KSTR + 64 * AT_VSTR;

    const int tid = threadIdx.x;
    const int warp = tid >> 5, lane = tid & 31;
    const int g = lane >> 2, tg = lane & 3;
    const int qt = blockIdx.x, h = blockIdx.y, b = blockIdx.z;
    const int q0 = qt * 64;
    const int L = seq_lens[b];
    const int bh = b * NH + h;
    const uint32_t* Qb = Qr + ((size_t)bh * S_LEN + q0) * HD;
    const uint32_t* Kb = Kr + (size_t)bh * S_LEN * HD;
    const uint32_t* Vb = Vr + (size_t)bh * S_LEN * HD;

    // stage Q (already tf32, pre-scaled) into Ksm
#pragma unroll
    for (int j = 0; j < 8; j++) {
        int i = tid + j * 128;
        int r = i >> 4, c = (i & 15) * 4;
        *(uint4*)&Ksm[r * AT_KSTR + c] = *(const uint4*)&Qb[(size_t)r * HD + c];
    }
    __syncthreads();

    // register-resident Q A-fragments
    uint32_t qa[8][4];
    const int mrow = warp * 16;
#pragma unroll
    for (int ks = 0; ks < 8; ks++) {
        qa[ks][0] = Ksm[(mrow + g) * AT_KSTR + 8 * ks + tg];
        qa[ks][1] = Ksm[(mrow + g + 8) * AT_KSTR + 8 * ks + tg];
        qa[ks][2] = Ksm[(mrow + g) * AT_KSTR + 8 * ks + tg + 4];
        qa[ks][3] = Ksm[(mrow + g + 8) * AT_KSTR + 8 * ks + tg + 4];
    }

    float o[8][4];
#pragma unroll
    for (int nt = 0; nt < 8; nt++)
#pragma unroll
        for (int r = 0; r < 4; r++) o[nt][r] = 0.f;
    float m0 = -1e30f, m1 = -1e30f, l0 = 0.f, l1 = 0.f;
    const int qg0 = q0 + mrow + g, qg1 = qg0 + 8;
    const int kmax0 = (qg0 < L) ? L : S_LEN;
    const int kmax1 = (qg1 < L) ? L : S_LEN;

    const int ntiles = (q0 + 63 < L) ? ((L + 63) >> 6) : (S_LEN >> 6);
    uint32_t* Pw = Psm + warp * 16 * AT_KSTR;

    for (int kt = 0; kt < ntiles; kt++) {
        __syncthreads();
        const uint32_t* Kt = Kb + (size_t)kt * 64 * HD;
        const uint32_t* Vt = Vb + (size_t)kt * 64 * HD;
#pragma unroll
        for (int j = 0; j < 8; j++) {
            int i = tid + j * 128;
            int r = i >> 4, c = (i & 15) * 4;
            *(uint4*)&Ksm[r * AT_KSTR + c] = *(const uint4*)&Kt[(size_t)r * HD + c];
            *(uint4*)&Vsm[r * AT_VSTR + c] = *(const uint4*)&Vt[(size_t)r * HD + c];
        }
        __syncthreads();

        // S = Q @ K^T
        float s[8][4];
#pragma unroll
        for (int nt = 0; nt < 8; nt++)
#pragma unroll
            for (int r = 0; r < 4; r++) s[nt][r] = 0.f;
#pragma unroll
        for (int ks = 0; ks < 8; ks++) {
#pragma unroll
            for (int nt = 0; nt < 8; nt++) {
                uint32_t bfr[2];
                bfr[0] = Ksm[(8 * nt + g) * AT_KSTR + 8 * ks + tg];
                bfr[1] = Ksm[(8 * nt + g) * AT_KSTR + 8 * ks + tg + 4];
                mma_tf32(s[nt], qa[ks], bfr);
            }
        }

        // mask
        if ((kt + 1) * 64 > L) {
            const int cb = kt * 64 + 2 * tg;
#pragma unroll
            for (int nt = 0; nt < 8; nt++) {
                const int c0 = cb + 8 * nt, c1 = c0 + 1;
                if (c0 >= kmax0) s[nt][0] = -1e30f;
                if (c1 >= kmax0) s[nt][1] = -1e30f;
                if (c0 >= kmax1) s[nt][2] = -1e30f;
                if (c1 >= kmax1) s[nt][3] = -1e30f;
            }
        }

        // online softmax
        float mx0 = -1e30f, mx1 = -1e30f;
#pragma unroll
        for (int nt = 0; nt < 8; nt++) {
            mx0 = fmaxf(mx0, fmaxf(s[nt][0], s[nt][1]));
            mx1 = fmaxf(mx1, fmaxf(s[nt][2], s[nt][3]));
        }
        mx0 = fmaxf(mx0, __shfl_xor_sync(0xffffffffu, mx0, 1));
        mx0 = fmaxf(mx0, __shfl_xor_sync(0xffffffffu, mx0, 2));
        mx1 = fmaxf(mx1, __shfl_xor_sync(0xffffffffu, mx1, 1));
        mx1 = fmaxf(mx1, __shfl_xor_sync(0xffffffffu, mx1, 2));
        const float mn0 = fmaxf(m0, mx0), mn1 = fmaxf(m1, mx1);
        const float a0 = __expf(m0 - mn0), a1 = __expf(m1 - mn1);
        float ls0 = 0.f, ls1 = 0.f;
#pragma unroll
        for (int nt = 0; nt < 8; nt++) {
            s[nt][0] = __expf(s[nt][0] - mn0); ls0 += s[nt][0];
            s[nt][1] = __expf(s[nt][1] - mn0); ls0 += s[nt][1];
            s[nt][2] = __expf(s[nt][2] - mn1); ls1 += s[nt][2];
            s[nt][3] = __expf(s[nt][3] - mn1); ls1 += s[nt][3];
        }
        ls0 += __shfl_xor_sync(0xffffffffu, ls0, 1);
        ls0 += __shfl_xor_sync(0xffffffffu, ls0, 2);
        ls1 += __shfl_xor_sync(0xffffffffu, ls1, 1);
        ls1 += __shfl_xor_sync(0xffffffffu, ls1, 2);
        l0 = l0 * a0 + ls0;  l1 = l1 * a1 + ls1;
        m0 = mn0;  m1 = mn1;
#pragma unroll
        for (int nt = 0; nt < 8; nt++) {
            o[nt][0] *= a0; o[nt][1] *= a0;
            o[nt][2] *= a1; o[nt][3] *= a1;
        }

        // P -> per-warp smem patch (tf32)
#pragma unroll
        for (int nt = 0; nt < 8; nt++) {
            const int cc = 8 * nt + 2 * tg;
            Pw[g * AT_KSTR + cc]           = f2tf32(s[nt][0]);
            Pw[g * AT_KSTR + cc + 1]       = f2tf32(s[nt][1]);
            Pw[(g + 8) * AT_KSTR + cc]     = f2tf32(s[nt][2]);
            Pw[(g + 8) * AT_KSTR + cc + 1] = f2tf32(s[nt][3]);
        }
        __syncwarp();

        // O += P @ V
#pragma unroll
        for (int ks = 0; ks < 8; ks++) {
            uint32_t pa[4];
            pa[0] = Pw[g * AT_KSTR + 8 * ks + tg];
            pa[1] = Pw[(g + 8) * AT_KSTR + 8 * ks + tg];
            pa[2] = Pw[g * AT_KSTR + 8 * ks + tg + 4];
            pa[3] = Pw[(g + 8) * AT_KSTR + 8 * ks + tg + 4];
#pragma unroll
            for (int nt = 0; nt < 8; nt++) {
                uint32_t vb[2];
                vb[0] = Vsm[(8 * ks + tg) * AT_VSTR + 8 * nt + g];
                vb[1] = Vsm[(8 * ks + tg + 4) * AT_VSTR + 8 * nt + g];
                mma_tf32(o[nt], pa, vb);
            }
        }
        __syncwarp();
    }

    // epilogue: normalize, write as tf32 patterns (consumed by WO gemm)
    const float i0 = 1.f / l0, i1 = 1.f / l1;
    uint32_t* d0 = O + ((size_t)b * S_LEN + qg0) * DIM + h * HD;
    uint32_t* d1 = O + ((size_t)b * S_LEN + qg1) * DIM + h * HD;
#pragma unroll
    for (int nt = 0; nt < 8; nt++) {
        const int cc = 8 * nt + 2 * tg;
        *(uint2*)&d0[cc] = make_uint2(f2tf32(o[nt][0] * i0), f2tf32(o[nt][1] * i0));
        *(uint2*)&d1[cc] = make_uint2(f2tf32(o[nt][2] * i1), f2tf32(o[nt][3] * i1));
    }
}

// ---------------- launch -----------------------------------------------------
extern "C" void kernel_launch(void* const* d_in, const int* in_sizes, int n_in,
                              void* d_out, int out_size)
{
    const float* x   = (const float*)d_in[0];
    const int*   seq = (const int*)  d_in[1];
    const float* wq  = (const float*)d_in[2];
    const float* wk  = (const float*)d_in[3];
    const float* wv  = (const float*)d_in[4];
    const float* wo  = (const float*)d_in[5];
    float* out = (float*)d_out;

    float *Qp, *Kp, *Vp;
    uint32_t *Qr, *Kr, *Vr, *Oa, *xt, *wqt, *wkt, *wvt, *wot;
    cudaGetSymbolAddress((void**)&Qp, g_Qp);
    cudaGetSymbolAddress((void**)&Kp, g_Kp);
    cudaGetSymbolAddress((void**)&Vp, g_Vp);
    cudaGetSymbolAddress((void**)&Qr, g_Qr);
    cudaGetSymbolAddress((void**)&Kr, g_Kr);
    cudaGetSymbolAddress((void**)&Vr, g_Vr);
    cudaGetSymbolAddress((void**)&Oa, g_O);
    cudaGetSymbolAddress((void**)&xt, g_xt);
    cudaGetSymbolAddress((void**)&wqt, g_wqt);
    cudaGetSymbolAddress((void**)&wkt, g_wkt);
    cudaGetSymbolAddress((void**)&wvt, g_wvt);
    cudaGetSymbolAddress((void**)&wot, g_wot);

    cudaFuncSetAttribute(qkv_gemm,
                         cudaFuncAttributeMaxDynamicSharedMemorySize, G_SMEM_TOTAL);
    cudaFuncSetAttribute(attn_mma,
                         cudaFuncAttributeMaxDynamicSharedMemorySize, AT_SMEM);

    // prepass: convert x + weights to tf32
    cvt_tf32<<<(MROWS * DIM) / 1024, 256>>>(x, xt);
    cvt_tf32<<<(DIM * DIM) / 1024, 256>>>(wq, wqt);
    cvt_tf32<<<(DIM * DIM) / 1024, 256>>>(wk, wkt);
    cvt_tf32<<<(DIM * DIM) / 1024, 256>>>(wv, wvt);
    cvt_tf32<<<(DIM * DIM) / 1024, 256>>>(wo, wot);

    // fused QKV projections (grid.z selects weight/output)
    qkv_gemm<<<dim3(DIM / 128, MROWS / 128, 3), 256, G_SMEM_TOTAL>>>(
        xt, wqt, wkt, wvt, Qp, Kp, Vp);

    rope_reshape<<<(B_SZ * S_LEN * NH * 32) / 256, 256>>>(Qp, Kp, Vp, Qr, Kr, Vr);

    attn_mma<<<dim3(S_LEN / 64, NH, B_SZ), 128, AT_SMEM>>>(Qr, Kr, Vr, seq, Oa);

    // output projection (single z-slice)
    qkv_gemm<<<dim3(DIM / 128, MROWS / 128, 1), 256, G_SMEM_TOTAL>>>(
        Oa, wot, wot, wot, out, out, out);
}